// round 6
// baseline (speedup 1.0000x reference)
#include <cuda_runtime.h>
#include <cuda_fp16.h>

#define NMAX 100000
#define D 64
#define CAP 64             // per-row bucket capacity (Poisson(16): P(deg>=64)*N ~ 1e-20)
#define FULL 0xffffffffu

typedef unsigned long long u64;

// Scratch (no device allocation). __device__ globals are zero-initialized.
__device__ __half g_hid[NMAX * D];            // 12.8 MB (fp16 hidden)
__device__ int    g_cnt[NMAX];                // degree counters; reset by SpmmC each call
__device__ int2   g_edge[(size_t)NMAX * CAP]; // 51.2 MB row buckets: (col, val-bits)

__device__ __forceinline__ float wsum(float v) {
#pragma unroll
    for (int o = 16; o; o >>= 1) v += __shfl_xor_sync(FULL, v, o);
    return v;
}

// fast artanh for x in [0, 1): 0.5*ln((1+x)/(1-x)); ~1e-6 rel err
__device__ __forceinline__ float artanh_f(float x) {
    x = fminf(x, 1.0f - 1e-7f);
    return 0.5f * __logf(__fdividef(1.0f + x, 1.0f - x));
}

__device__ __forceinline__ u64 ffma2(u64 a, u64 b, u64 c) {
    u64 d;
    asm("fma.rn.f32x2 %0, %1, %2, %3;" : "=l"(d) : "l"(a), "l"(b), "l"(c));
    return d;
}
__device__ __forceinline__ float2 unpack2(u64 v) {
    float2 r;
    asm("mov.b64 {%0, %1}, %2;" : "=f"(r.x), "=f"(r.y) : "l"(v));
    return r;
}
__device__ __forceinline__ u64 pack2(float lo, float hi) {
    u64 v;
    asm("mov.b64 %0, {%1, %2};" : "=l"(v) : "f"(lo), "f"(hi));
    return v;
}

// ---------------------------------------------------------------------------
// Kernel AF: blocks [0, NA) run the fused linear+mobius+logmap0 (-> g_hid fp16);
//            blocks [NA, ...) bucket edges by destination row (g_edge/g_cnt).
// The two halves touch disjoint state, so Fill hides under A's compute.
// ---------------------------------------------------------------------------
__global__ void __launch_bounds__(256) kernelAF(
    const float* __restrict__ x, const float* __restrict__ W,
    const float* __restrict__ ev, const int* __restrict__ rows,
    const int* __restrict__ cols, int N, int E, int NA)
{
    if ((int)blockIdx.x >= NA) {
        // ---- Fill path: 8 edges per thread, independent (MLP=8) ----
        int e0 = (blockIdx.x - NA) * 2048 + threadIdx.x;
#pragma unroll
        for (int u = 0; u < 8; u++) {
            int e = e0 + u * 256;
            if (e < E) {
                int r = __ldg(&rows[e]);
                int pos = atomicAdd(&g_cnt[r], 1);
                if (pos < CAP)
                    g_edge[(size_t)r * CAP + pos] =
                        make_int2(__ldg(&cols[e]), __float_as_int(__ldg(&ev[e])));
            }
        }
        return;
    }

    // ---- A path: warp handles 8 rows as 4 packed row-pairs ----
    __shared__ float  Ws[D * 65];     // W^T, padded
    __shared__ float2 Xp[8][D][4];    // packed x row-pairs

    const int tid  = threadIdx.x;
    const int warp = tid >> 5;
    const int lane = tid & 31;

    for (int i = tid; i < D * D; i += 256) {
        int d = i >> 6, k = i & 63;
        Ws[k * 65 + d] = W[i];
    }

    const int base = (blockIdx.x * 8 + warp) * 8;
#pragma unroll
    for (int p = 0; p < 4; p++) {
        int r0 = base + 2 * p, r1 = r0 + 1;
        float a0 = (r0 < N) ? x[r0 * D + lane]      : 0.f;
        float a1 = (r0 < N) ? x[r0 * D + lane + 32] : 0.f;
        float b0 = (r1 < N) ? x[r1 * D + lane]      : 0.f;
        float b1 = (r1 < N) ? x[r1 * D + lane + 32] : 0.f;
        Xp[warp][lane][p]      = make_float2(a0, b0);
        Xp[warp][lane + 32][p] = make_float2(a1, b1);
    }
    __syncthreads();
    if (base >= N) return;

    u64 acc[4][2];
#pragma unroll
    for (int p = 0; p < 4; p++) { acc[p][0] = 0ull; acc[p][1] = 0ull; }

#pragma unroll 16
    for (int k = 0; k < D; k++) {
        float w0f = Ws[k * 65 + lane];
        float w1f = Ws[k * 65 + lane + 32];
        u64 w0 = pack2(w0f, w0f);
        u64 w1 = pack2(w1f, w1f);
        const u64* xr = reinterpret_cast<const u64*>(&Xp[warp][k][0]);
#pragma unroll
        for (int p = 0; p < 4; p++) {
            u64 xp = xr[p];
            acc[p][0] = ffma2(w0, xp, acc[p][0]);
            acc[p][1] = ffma2(w1, xp, acc[p][1]);
        }
    }

#pragma unroll
    for (int p = 0; p < 4; p++) {
        float2 c0 = unpack2(acc[p][0]);   // {mx[r0][lane],    mx[r1][lane]}
        float2 c1 = unpack2(acc[p][1]);   // {mx[r0][lane+32], mx[r1][lane+32]}
#pragma unroll
        for (int q = 0; q < 2; q++) {
            int row = base + 2 * p + q;
            if (row < N) {                 // uniform across warp
                float a0 = q ? c0.y : c0.x;
                float a1 = q ? c1.y : c1.x;
                float x0 = x[row * D + lane];        // L1 hits
                float x1 = x[row * D + lane + 32];
                float xn  = fmaxf(sqrtf(wsum(x0 * x0 + x1 * x1)), 1e-15f);
                float mxn = fmaxf(sqrtf(wsum(a0 * a0 + a1 * a1)), 1e-15f);
                unsigned bz = __ballot_sync(FULL, (a0 == 0.f) && (a1 == 0.f));
                float t = tanhf(__fdividef(mxn, xn) * artanh_f(xn));
                float scale = __fdividef(t, mxn);
                if (bz == FULL) scale = 0.f;
                // |res| = t analytically (res = mx*scale, scale >= 0)
                float pn = fmaxf(t, 1e-15f);
                float hs = __fdividef(artanh_f(pn), pn) * scale;
                g_hid[row * D + lane]      = __float2half_rn(a0 * hs);
                g_hid[row * D + lane + 32] = __float2half_rn(a1 * hs);
            }
        }
    }
}

// ---------------------------------------------------------------------------
// Fused SpMM (fp16 gather, fp32 accumulate) + expmap0 -> relu(logmap0)
// -> expmap0 -> proj => out.  One warp per row; lane owns features
// (2*lane, 2*lane+1) via one __half2 load per edge.  Resets g_cnt.
// ---------------------------------------------------------------------------
__global__ void __launch_bounds__(256) kernelSpmmC(float* __restrict__ out, int N)
{
    int row = blockIdx.x * 8 + (threadIdx.x >> 5);
    if (row >= N) return;
    int lane = threadIdx.x & 31;
    int deg = min(g_cnt[row], CAP);
    if (lane == 0) g_cnt[row] = 0;          // restore invariant for next call
    const int2* eb = &g_edge[(size_t)row * CAP];
    const __half2* hp = reinterpret_cast<const __half2*>(g_hid);

    float acc0 = 0.f, acc1 = 0.f;
    for (int s = 0; s < deg; s += 32) {
        int m = min(32, deg - s);
        u64 ep = 0ull;
        if (lane < m) {
            int2 er = __ldg(&eb[s + lane]);
            ep = pack2(__int_as_float(er.x), __int_as_float(er.y));
        }
        int j = 0;
        for (; j + 4 <= m; j += 4) {
#pragma unroll
            for (int u = 0; u < 4; u++) {
                u64 q = __shfl_sync(FULL, ep, j + u);
                float2 cv = unpack2(q);
                int c = __float_as_int(cv.x);
                float2 hf = __half22float2(__ldg(&hp[(size_t)c * 32 + lane]));
                acc0 = fmaf(cv.y, hf.x, acc0);
                acc1 = fmaf(cv.y, hf.y, acc1);
            }
        }
        for (; j < m; j++) {
            u64 q = __shfl_sync(FULL, ep, j);
            float2 cv = unpack2(q);
            int c = __float_as_int(cv.x);
            float2 hf = __half22float2(__ldg(&hp[(size_t)c * 32 + lane]));
            acc0 = fmaf(cv.y, hf.x, acc0);
            acc1 = fmaf(cv.y, hf.y, acc1);
        }
    }

    // expmap0: |p| = tanh(un) analytically
    float un = fmaxf(sqrtf(wsum(acc0 * acc0 + acc1 * acc1)), 1e-15f);
    float tn = tanhf(un);
    float ps = __fdividef(tn, un);
    float pn = fmaxf(tn, 1e-15f);
    // relu(logmap0(p))
    float as = __fdividef(artanh_f(pn), pn) * ps;
    float xt0 = fmaxf(as * acc0, 0.f), xt1 = fmaxf(as * acc1, 0.f);
    // expmap0; |out| = tanh(xn)
    float xn = fmaxf(sqrtf(wsum(xt0 * xt0 + xt1 * xt1)), 1e-15f);
    float txn = tanhf(xn);
    float os = __fdividef(txn, xn);
    float o0 = os * xt0, o1 = os * xt1;
    // proj
    float on = fmaxf(txn, 1e-15f);
    float mxn = 1.0f - 1e-5f;
    if (on > mxn) { float f = __fdividef(mxn, on); o0 *= f; o1 *= f; }
    reinterpret_cast<float2*>(out)[row * 32 + lane] = make_float2(o0, o1);
}

// ---------------------------------------------------------------------------
extern "C" void kernel_launch(void* const* d_in, const int* in_sizes, int n_in,
                              void* d_out, int out_size)
{
    const float* x    = (const float*)d_in[0];
    const float* W    = (const float*)d_in[1];
    const float* ev   = (const float*)d_in[2];
    const int*   rows = (const int*)d_in[3];
    const int*   cols = (const int*)d_in[4];
    float* out = (float*)d_out;

    int N = in_sizes[0] / D;
    int E = in_sizes[2];

    int NA = (N + 63) / 64;           // A blocks (8 rows/warp * 8 warps)
    int NF = (E + 2047) / 2048;       // Fill blocks (8 edges/thread)
    kernelAF<<<NA + NF, 256>>>(x, W, ev, rows, cols, N, E, NA);
    kernelSpmmC<<<(N + 7) / 8, 256>>>(out, N);
}